// round 14
// baseline (speedup 1.0000x reference)
#include <cuda_runtime.h>
#include <cuda_fp16.h>
#include <cstdint>

// Problem constants
#define BATCH 8
#define NPIX  4096          // 64*64
#define CIN   256
#define DHEAD 32
#define MROWS (BATCH*NPIX)  // 32768

#define QT 64               // q rows per attn CTA (4 warps x 16 rows)
#define MT 64               // k/v rows per inner tile

// smem strides (in halves). 40 halves = 80B rows: 16B aligned.
#define TS 40
#define WQS 104
#define WOS2 264            // Wo tile stride: 256+8 halves; 528B rows = 33*16B

#define LOG2E 1.4426950408889634f

// fp16 scratch (device globals; no runtime allocation allowed)
__device__ __half g_q[MROWS * DHEAD];
__device__ __half g_k[MROWS * DHEAD];
__device__ __half g_v[MROWS * DHEAD];

// ---------------------------------------------------------------------------
// helpers
// ---------------------------------------------------------------------------
__device__ __forceinline__ uint32_t pack2(float lo, float hi) {
    __half2 h = __floats2half2_rn(lo, hi);
    return *reinterpret_cast<uint32_t*>(&h);
}
__device__ __forceinline__ uint32_t h2exp2(uint32_t u) {
    uint32_t r;
    asm("ex2.approx.f16x2 %0, %1;" : "=r"(r) : "r"(u));
    return r;
}

__device__ __forceinline__ void mma_f16(float* d, const uint32_t* a,
                                        uint32_t b0, uint32_t b1, const float* c)
{
    asm("mma.sync.aligned.m16n8k16.row.col.f32.f16.f16.f32 "
        "{%0,%1,%2,%3}, {%4,%5,%6,%7}, {%8,%9}, {%10,%11,%12,%13};"
        : "=f"(d[0]), "=f"(d[1]), "=f"(d[2]), "=f"(d[3])
        : "r"(a[0]), "r"(a[1]), "r"(a[2]), "r"(a[3]),
          "r"(b0), "r"(b1),
          "f"(c[0]), "f"(c[1]), "f"(c[2]), "f"(c[3]));
}

__device__ __forceinline__ void ldsm4(uint32_t* r, uint32_t addr) {
    asm volatile("ldmatrix.sync.aligned.m8n8.x4.shared.b16 {%0,%1,%2,%3}, [%4];"
                 : "=r"(r[0]), "=r"(r[1]), "=r"(r[2]), "=r"(r[3]) : "r"(addr));
}
__device__ __forceinline__ void ldsm4t(uint32_t* r, uint32_t addr) {
    asm volatile("ldmatrix.sync.aligned.m8n8.x4.trans.shared.b16 {%0,%1,%2,%3}, [%4];"
                 : "=r"(r[0]), "=r"(r[1]), "=r"(r[2]), "=r"(r[3]) : "r"(addr));
}

// ---------------------------------------------------------------------------
// Kernel 1: QKV projection (round-7 config, unchanged: 256 thr, M tile 128).
// X[32768,256] @ [Wq|Wk|Wv][256,96] + bias, ReLU -> g_q/g_k/g_v (fp16).
// ---------------------------------------------------------------------------
__global__ void __launch_bounds__(256) qkv_kernel(
    const float* __restrict__ x,
    const float* __restrict__ Wq, const float* __restrict__ bq,
    const float* __restrict__ Wk, const float* __restrict__ bk,
    const float* __restrict__ Wv, const float* __restrict__ bv)
{
    __shared__ __half Xs[2][128 * TS];
    __shared__ __half Ws[2][32 * WQS];
    __shared__ float bsm[96];

    const int tid = threadIdx.x;
    const int warp = tid >> 5, lane = tid & 31;
    const int gid = lane >> 2, tig = lane & 3;
    const int row0 = blockIdx.x * 128;

    const uint32_t xs_base = (uint32_t)__cvta_generic_to_shared(&Xs[0][0]);
    const uint32_t ws_base = (uint32_t)__cvta_generic_to_shared(&Ws[0][0]);
    const uint32_t XBUF = 128 * TS * 2;
    const uint32_t WBUF = 32 * WQS * 2;

    if (tid < 96) bsm[tid] = (tid < 32) ? bq[tid] : (tid < 64 ? bk[tid - 32] : bv[tid - 64]);

    const float* wmat[3] = {Wq, Wk, Wv};

    float acc[12][4];
#pragma unroll
    for (int nb = 0; nb < 12; nb++)
#pragma unroll
        for (int r = 0; r < 4; r++) acc[nb][r] = 0.f;

    float4 xr[4], wr[3];
#pragma unroll
    for (int it = 0; it < 4; it++) {
        int i = tid + it * 256;
        int r = i >> 3, c4 = i & 7;
        xr[it] = *(const float4*)(x + (size_t)(row0 + r) * CIN + c4 * 4);
    }
#pragma unroll
    for (int m = 0; m < 3; m++) {
        int kk = tid >> 3, c4 = tid & 7;
        wr[m] = *(const float4*)(wmat[m] + (size_t)kk * DHEAD + c4 * 4);
    }
#pragma unroll
    for (int it = 0; it < 4; it++) {
        int i = tid + it * 256;
        int r = i >> 3, c4 = i & 7;
        uint2 p; p.x = pack2(xr[it].x, xr[it].y); p.y = pack2(xr[it].z, xr[it].w);
        *(uint2*)&Xs[0][r * TS + c4 * 4] = p;
    }
#pragma unroll
    for (int m = 0; m < 3; m++) {
        int kk = tid >> 3, c4 = tid & 7;
        uint2 p; p.x = pack2(wr[m].x, wr[m].y); p.y = pack2(wr[m].z, wr[m].w);
        *(uint2*)&Ws[0][kk * WQS + m * 32 + c4 * 4] = p;
    }
    __syncthreads();

    for (int c = 0; c < 8; c++) {
        const int cur = c & 1;

        if (c + 1 < 8) {
            int kc = (c + 1) * 32;
#pragma unroll
            for (int it = 0; it < 4; it++) {
                int i = tid + it * 256;
                int r = i >> 3, c4 = i & 7;
                xr[it] = *(const float4*)(x + (size_t)(row0 + r) * CIN + kc + c4 * 4);
            }
#pragma unroll
            for (int m = 0; m < 3; m++) {
                int kk = tid >> 3, c4 = tid & 7;
                wr[m] = *(const float4*)(wmat[m] + (size_t)(kc + kk) * DHEAD + c4 * 4);
            }
        }

        uint32_t a[2][4];
#pragma unroll
        for (int ks = 0; ks < 2; ks++) {
            uint32_t addr = xs_base + cur * XBUF +
                ((warp * 16 + ((lane >> 3) & 1) * 8 + (lane & 7)) * TS) * 2 +
                (ks * 16 + (lane >> 4) * 8) * 2;
            ldsm4(a[ks], addr);
        }
#pragma unroll
        for (int ks = 0; ks < 2; ks++) {
#pragma unroll
            for (int nbp = 0; nbp < 6; nbp++) {
                uint32_t wb[4];
                uint32_t addr = ws_base + cur * WBUF +
                    ((ks * 16 + ((lane >> 3) & 1) * 8 + (lane & 7)) * WQS) * 2 +
                    (nbp * 16 + (lane >> 4) * 8) * 2;
                ldsm4t(wb, addr);
                mma_f16(acc[2 * nbp],     a[ks], wb[0], wb[1], acc[2 * nbp]);
                mma_f16(acc[2 * nbp + 1], a[ks], wb[2], wb[3], acc[2 * nbp + 1]);
            }
        }

        if (c + 1 < 8) {
#pragma unroll
            for (int it = 0; it < 4; it++) {
                int i = tid + it * 256;
                int r = i >> 3, c4 = i & 7;
                uint2 p; p.x = pack2(xr[it].x, xr[it].y); p.y = pack2(xr[it].z, xr[it].w);
                *(uint2*)&Xs[cur ^ 1][r * TS + c4 * 4] = p;
            }
#pragma unroll
            for (int m = 0; m < 3; m++) {
                int kk = tid >> 3, c4 = tid & 7;
                uint2 p; p.x = pack2(wr[m].x, wr[m].y); p.y = pack2(wr[m].z, wr[m].w);
                *(uint2*)&Ws[cur ^ 1][kk * WQS + m * 32 + c4 * 4] = p;
            }
        }
        __syncthreads();
    }

#pragma unroll
    for (int nb = 0; nb < 12; nb++) {
        int cc = nb * 8 + 2 * tig;
        float b0 = bsm[cc], b1 = bsm[cc + 1];
        int r0 = row0 + warp * 16 + gid;
        __half* dst; int col;
        if (nb < 4)      { dst = g_q; col = cc; }
        else if (nb < 8) { dst = g_k; col = cc - 32; }
        else             { dst = g_v; col = cc - 64; }
        *(uint32_t*)(dst + (size_t)r0 * DHEAD + col) =
            pack2(fmaxf(acc[nb][0] + b0, 0.f), fmaxf(acc[nb][1] + b1, 0.f));
        *(uint32_t*)(dst + (size_t)(r0 + 8) * DHEAD + col) =
            pack2(fmaxf(acc[nb][2] + b0, 0.f), fmaxf(acc[nb][3] + b1, 0.f));
    }
}

// ---------------------------------------------------------------------------
// Kernel 2: flash attention + fused output projection.
//  NEW: QT=64, 4-warp CTAs, 4 CTAs/SM -> 4 INDEPENDENT sync domains per SM
//  (phase decoupling: softmax of one CTA overlaps mma of another).
//  Mainloop per warp: byte-identical to round 13 (best measured).
// Grid (64, 8) = 512 CTAs, double-buffered K/V.
// ---------------------------------------------------------------------------
__global__ void __launch_bounds__(128, 4) attn_kernel(
    const float* __restrict__ Wo,
    const float* __restrict__ bo,
    float* __restrict__ out)
{
    __shared__ __half Ks[2][MT * TS];      // 2 x 5 KB
    __shared__ __half Vs[2][MT * TS];      // 2 x 5 KB
    __shared__ __half Wos[32 * WOS2];      // 16.5 KB
    __shared__ float bos[256];

    const int b   = blockIdx.y;
    const int qt  = blockIdx.x;
    const int tid = threadIdx.x;
    const int warp = tid >> 5, lane = tid & 31;
    const int gid = lane >> 2, tig = lane & 3;

    const uint32_t ks_base = (uint32_t)__cvta_generic_to_shared(&Ks[0][0]);
    const uint32_t vs_base = (uint32_t)__cvta_generic_to_shared(&Vs[0][0]);
    const uint32_t wo_base = (uint32_t)__cvta_generic_to_shared(&Wos[0]);
    const uint32_t BUF = MT * TS * 2;

    // constant ones B-frag for the l accumulator column
    const uint32_t ones = (gid == 0) ? 0x3C003C00u : 0u;

    const __half* qg = g_q + ((size_t)b * NPIX + (size_t)qt * QT + warp * 16) * DHEAD;
    const __half* kg = g_k + (size_t)b * NPIX * DHEAD;
    const __half* vg = g_v + (size_t)b * NPIX * DHEAD;

    // ---- prologue: Wo -> smem (fp16), bias -> smem (one-time) ----
    bos[tid] = bo[tid];
    bos[tid + 128] = bo[tid + 128];
#pragma unroll
    for (int it = 0; it < 16; it++) {
        int i = tid + it * 128;            // 0..2047 float4s
        int kk = i >> 6, c4 = i & 63;
        float4 v = *(const float4*)(Wo + (size_t)kk * CIN + c4 * 4);
        uint2 p; p.x = pack2(v.x, v.y); p.y = pack2(v.z, v.w);
        *(uint2*)&Wos[kk * WOS2 + c4 * 4] = p;
    }

    uint32_t qa[2][4];
#pragma unroll
    for (int ks = 0; ks < 2; ks++) {
        qa[ks][0] = *(const uint32_t*)(qg + (size_t)(gid)     * DHEAD + ks * 16 + 2 * tig);
        qa[ks][1] = *(const uint32_t*)(qg + (size_t)(gid + 8) * DHEAD + ks * 16 + 2 * tig);
        qa[ks][2] = *(const uint32_t*)(qg + (size_t)(gid)     * DHEAD + ks * 16 + 8 + 2 * tig);
        qa[ks][3] = *(const uint32_t*)(qg + (size_t)(gid + 8) * DHEAD + ks * 16 + 8 + 2 * tig);
    }

    // O[0..3] = output d-blocks, O[4] = l (row-sum) block
    float O[5][4];
#pragma unroll
    for (int nb = 0; nb < 5; nb++)
#pragma unroll
        for (int r = 0; r < 4; r++) O[nb][r] = 0.f;
    float mi0 = -1e30f, mi1 = -1e30f;

    // staging: 128 threads x 2 uint4 each for K and V (64 rows x 32 halves)
    const int sr0 = tid >> 2, sc0 = (tid & 3) * 8;           // i = tid
    const int sr1 = (tid + 128) >> 2, sc1 = sc0;             // i = tid+128
    uint4 kpre[2], vpre[2];
    kpre[0] = *(const uint4*)(kg + (size_t)sr0 * DHEAD + sc0);
    kpre[1] = *(const uint4*)(kg + (size_t)sr1 * DHEAD + sc1);
    vpre[0] = *(const uint4*)(vg + (size_t)sr0 * DHEAD + sc0);
    vpre[1] = *(const uint4*)(vg + (size_t)sr1 * DHEAD + sc1);
    *(uint4*)&Ks[0][sr0 * TS + sc0] = kpre[0];
    *(uint4*)&Ks[0][sr1 * TS + sc1] = kpre[1];
    *(uint4*)&Vs[0][sr0 * TS + sc0] = vpre[0];
    *(uint4*)&Vs[0][sr1 * TS + sc1] = vpre[1];
    __syncthreads();

    for (int mt = 0; mt < NPIX / MT; mt++) {
        const int cur = mt & 1;

        if (mt + 1 < NPIX / MT) {
            const __half* kt = kg + (size_t)(mt + 1) * MT * DHEAD;
            const __half* vt = vg + (size_t)(mt + 1) * MT * DHEAD;
            kpre[0] = *(const uint4*)(kt + (size_t)sr0 * DHEAD + sc0);
            kpre[1] = *(const uint4*)(kt + (size_t)sr1 * DHEAD + sc1);
            vpre[0] = *(const uint4*)(vt + (size_t)sr0 * DHEAD + sc0);
            vpre[1] = *(const uint4*)(vt + (size_t)sr1 * DHEAD + sc1);
        }

        // ---- mma1: S(16x64) = Q K^T ----
        float S[8][4];
#pragma unroll
        for (int nb = 0; nb < 8; nb++) {
#pragma unroll
            for (int r = 0; r < 4; r++) S[nb][r] = 0.f;
            uint32_t kb[4];
            uint32_t addr = ks_base + cur * BUF +
                ((nb * 8 + (lane & 7)) * TS) * 2 + (lane >> 3) * 16;
            ldsm4(kb, addr);
            mma_f16(S[nb], qa[0], kb[0], kb[1], S[nb]);
            mma_f16(S[nb], qa[1], kb[2], kb[3], S[nb]);
        }

        // ---- online softmax (rows gid, gid+8) ----
        float rm0 = -1e30f, rm1 = -1e30f;
#pragma unroll
        for (int nb = 0; nb < 8; nb++) {
            rm0 = fmaxf(rm0, fmaxf(S[nb][0], S[nb][1]));
            rm1 = fmaxf(rm1, fmaxf(S[nb][2], S[nb][3]));
        }
        rm0 = fmaxf(rm0, __shfl_xor_sync(0xffffffffu, rm0, 1));
        rm0 = fmaxf(rm0, __shfl_xor_sync(0xffffffffu, rm0, 2));
        rm1 = fmaxf(rm1, __shfl_xor_sync(0xffffffffu, rm1, 1));
        rm1 = fmaxf(rm1, __shfl_xor_sync(0xffffffffu, rm1, 2));

        float nm0 = fmaxf(mi0, rm0), nm1 = fmaxf(mi1, rm1);
        float corr0 = exp2f((mi0 - nm0) * LOG2E);
        float corr1 = exp2f((mi1 - nm1) * LOG2E);
        mi0 = nm0; mi1 = nm1;
        const float nc0 = nm0 * (-LOG2E), nc1 = nm1 * (-LOG2E);

        // exp in fp16x2, pack directly into mma2 A-fragments (1 FFMA/elem)
        uint32_t P[4][4];
#pragma unroll
        for (int nb = 0; nb < 8; nb++) {
            float u0 = fmaf(S[nb][0], LOG2E, nc0);
            float u1 = fmaf(S[nb][1], LOG2E, nc0);
            float u2 = fmaf(S[nb][2], LOG2E, nc1);
            float u3 = fmaf(S[nb][3], LOG2E, nc1);
            int ks2 = nb >> 1, hi = (nb & 1) * 2;
            P[ks2][hi]     = h2exp2(pack2(u0, u1));
            P[ks2][hi + 1] = h2exp2(pack2(u2, u3));
        }

        // rescale O (incl. l block)
#pragma unroll
        for (int nb = 0; nb < 5; nb++) {
            O[nb][0] *= corr0; O[nb][1] *= corr0;
            O[nb][2] *= corr1; O[nb][3] *= corr1;
        }

        // ---- mma2: O(16x32) += P V ;  l += P @ ones ----
#pragma unroll
        for (int ks2 = 0; ks2 < 4; ks2++) {
            const uint32_t* a = P[ks2];
#pragma unroll
            for (int dbp = 0; dbp < 2; dbp++) {
                uint32_t vb[4];
                uint32_t addr = vs_base + cur * BUF +
                    ((ks2 * 16 + ((lane >> 3) & 1) * 8 + (lane & 7)) * TS) * 2 +
                    dbp * 32 + (lane >> 4) * 16;
                ldsm4t(vb, addr);
                mma_f16(O[2 * dbp],     a, vb[0], vb[1], O[2 * dbp]);
                mma_f16(O[2 * dbp + 1], a, vb[2], vb[3], O[2 * dbp + 1]);
            }
            mma_f16(O[4], a, ones, ones, O[4]);
        }

        if (mt + 1 < NPIX / MT) {
            *(uint4*)&Ks[cur ^ 1][sr0 * TS + sc0] = kpre[0];
            *(uint4*)&Ks[cur ^ 1][sr1 * TS + sc1] = kpre[1];
            *(uint4*)&Vs[cur ^ 1][sr0 * TS + sc0] = vpre[0];
            *(uint4*)&Vs[cur ^ 1][sr1 * TS + sc1] = vpre[1];
        }
        __syncthreads();
    }

    // ---- fused epilogue: out = ReLU((O/l) @ Wo + bo) ----
    float l0 = __shfl_sync(0xffffffffu, O[4][0], lane & 28);
    float l1 = __shfl_sync(0xffffffffu, O[4][2], lane & 28);
    float inv0 = 1.f / l0, inv1 = 1.f / l1;

    // Pack normalized O into proj A-fragments: aep[ks] covers k-cols 16ks..16ks+15.
    uint32_t aep[2][4];
#pragma unroll
    for (int ks = 0; ks < 2; ks++) {
        aep[ks][0] = pack2(O[2 * ks][0] * inv0, O[2 * ks][1] * inv0);
        aep[ks][1] = pack2(O[2 * ks][2] * inv1, O[2 * ks][3] * inv1);
        aep[ks][2] = pack2(O[2 * ks + 1][0] * inv0, O[2 * ks + 1][1] * inv0);
        aep[ks][3] = pack2(O[2 * ks + 1][2] * inv1, O[2 * ks + 1][3] * inv1);
    }

    const size_t base = (size_t)b * NPIX + (size_t)qt * QT + warp * 16;
#pragma unroll
    for (int h = 0; h < 2; h++) {          // two 128-col halves (bounds regs)
        float acc[16][4];
#pragma unroll
        for (int nb = 0; nb < 16; nb++)
#pragma unroll
            for (int r = 0; r < 4; r++) acc[nb][r] = 0.f;

#pragma unroll
        for (int ks = 0; ks < 2; ks++) {
#pragma unroll
            for (int nbp = 0; nbp < 8; nbp++) {
                uint32_t wb[4];
                uint32_t addr = wo_base +
                    ((ks * 16 + ((lane >> 3) & 1) * 8 + (lane & 7)) * WOS2) * 2 +
                    (h * 128 + nbp * 16 + (lane >> 4) * 8) * 2;
                ldsm4t(wb, addr);
                mma_f16(acc[2 * nbp],     aep[ks], wb[0], wb[1], acc[2 * nbp]);
                mma_f16(acc[2 * nbp + 1], aep[ks], wb[2], wb[3], acc[2 * nbp + 1]);
            }
        }

#pragma unroll
        for (int nb = 0; nb < 16; nb++) {
            int cc = h * 128 + nb * 8 + 2 * tig;
            float b0 = bos[cc], b1 = bos[cc + 1];
            float2 lo, hi;
            lo.x = fmaxf(acc[nb][0] + b0, 0.f); lo.y = fmaxf(acc[nb][1] + b1, 0.f);
            hi.x = fmaxf(acc[nb][2] + b0, 0.f); hi.y = fmaxf(acc[nb][3] + b1, 0.f);
            *(float2*)(out + (base + gid) * CIN + cc)     = lo;
            *(float2*)(out + (base + gid + 8) * CIN + cc) = hi;
        }
    }
}

// ---------------------------------------------------------------------------
extern "C" void kernel_launch(void* const* d_in, const int* in_sizes, int n_in,
                              void* d_out, int out_size)
{
    const float* x  = (const float*)d_in[0];
    const float* Wq = (const float*)d_in[1];
    const float* bq = (const float*)d_in[2];
    const float* Wk = (const float*)d_in[3];
    const float* bk = (const float*)d_in[4];
    const float* Wv = (const float*)d_in[5];
    const float* bv = (const float*)d_in[6];
    const float* Wo = (const float*)d_in[7];
    const float* bo = (const float*)d_in[8];
    float* out = (float*)d_out;

    qkv_kernel<<<MROWS / 128, 256>>>(x, Wq, bq, Wk, bk, Wv, bv);
    attn_kernel<<<dim3(NPIX / QT, BATCH), 128>>>(Wo, bo, out);
}

// round 15
// speedup vs baseline: 1.0778x; 1.0778x over previous
#include <cuda_runtime.h>
#include <cuda_fp16.h>
#include <cstdint>

// Problem constants
#define BATCH 8
#define NPIX  4096          // 64*64
#define CIN   256
#define DHEAD 32
#define MROWS (BATCH*NPIX)  // 32768

#define QT 64               // q rows per attn CTA (4 warps x 16 rows)
#define MT 64               // k/v rows per inner tile
#define KVH (NPIX/2)        // kv rows per split half = 2048
#define NTILES (KVH/MT)     // 32 tiles per half

// smem strides (in halves). 40 halves = 80B rows: 16B aligned.
#define TS 40
#define WQS 104
#define WOS 136

#define LOG2E 1.4426950408889634f

// fp16 scratch (device globals; no runtime allocation allowed)
__device__ __half g_q[MROWS * DHEAD];
__device__ __half g_k[MROWS * DHEAD];
__device__ __half g_v[MROWS * DHEAD];
// split-KV partials: unnormalized O (fp32) and (m, l) per row, per half
__device__ float  g_po[2 * MROWS * DHEAD];   // 8 MB
__device__ float2 g_ml[2 * MROWS];           // 0.5 MB

// ---------------------------------------------------------------------------
// helpers
// ---------------------------------------------------------------------------
__device__ __forceinline__ uint32_t pack2(float lo, float hi) {
    __half2 h = __floats2half2_rn(lo, hi);
    return *reinterpret_cast<uint32_t*>(&h);
}
__device__ __forceinline__ uint32_t h2exp2(uint32_t u) {
    uint32_t r;
    asm("ex2.approx.f16x2 %0, %1;" : "=r"(r) : "r"(u));
    return r;
}

__device__ __forceinline__ void mma_f16(float* d, const uint32_t* a,
                                        uint32_t b0, uint32_t b1, const float* c)
{
    asm("mma.sync.aligned.m16n8k16.row.col.f32.f16.f16.f32 "
        "{%0,%1,%2,%3}, {%4,%5,%6,%7}, {%8,%9}, {%10,%11,%12,%13};"
        : "=f"(d[0]), "=f"(d[1]), "=f"(d[2]), "=f"(d[3])
        : "r"(a[0]), "r"(a[1]), "r"(a[2]), "r"(a[3]),
          "r"(b0), "r"(b1),
          "f"(c[0]), "f"(c[1]), "f"(c[2]), "f"(c[3]));
}

__device__ __forceinline__ void ldsm4(uint32_t* r, uint32_t addr) {
    asm volatile("ldmatrix.sync.aligned.m8n8.x4.shared.b16 {%0,%1,%2,%3}, [%4];"
                 : "=r"(r[0]), "=r"(r[1]), "=r"(r[2]), "=r"(r[3]) : "r"(addr));
}
__device__ __forceinline__ void ldsm4t(uint32_t* r, uint32_t addr) {
    asm volatile("ldmatrix.sync.aligned.m8n8.x4.trans.shared.b16 {%0,%1,%2,%3}, [%4];"
                 : "=r"(r[0]), "=r"(r[1]), "=r"(r[2]), "=r"(r[3]) : "r"(addr));
}

__device__ __forceinline__ void cp16(uint32_t smem_addr, const void* gptr) {
    asm volatile("cp.async.cg.shared.global [%0], [%1], 16;"
                 :: "r"(smem_addr), "l"(gptr) : "memory");
}
__device__ __forceinline__ void cp_commit() {
    asm volatile("cp.async.commit_group;" ::: "memory");
}
__device__ __forceinline__ void cp_wait0() {
    asm volatile("cp.async.wait_group 0;" ::: "memory");
}

// ---------------------------------------------------------------------------
// Kernel 1: QKV projection (round-7 config, unchanged).
// ---------------------------------------------------------------------------
__global__ void __launch_bounds__(256) qkv_kernel(
    const float* __restrict__ x,
    const float* __restrict__ Wq, const float* __restrict__ bq,
    const float* __restrict__ Wk, const float* __restrict__ bk,
    const float* __restrict__ Wv, const float* __restrict__ bv)
{
    __shared__ __half Xs[2][128 * TS];
    __shared__ __half Ws[2][32 * WQS];
    __shared__ float bsm[96];

    const int tid = threadIdx.x;
    const int warp = tid >> 5, lane = tid & 31;
    const int gid = lane >> 2, tig = lane & 3;
    const int row0 = blockIdx.x * 128;

    const uint32_t xs_base = (uint32_t)__cvta_generic_to_shared(&Xs[0][0]);
    const uint32_t ws_base = (uint32_t)__cvta_generic_to_shared(&Ws[0][0]);
    const uint32_t XBUF = 128 * TS * 2;
    const uint32_t WBUF = 32 * WQS * 2;

    if (tid < 96) bsm[tid] = (tid < 32) ? bq[tid] : (tid < 64 ? bk[tid - 32] : bv[tid - 64]);

    const float* wmat[3] = {Wq, Wk, Wv};

    float acc[12][4];
#pragma unroll
    for (int nb = 0; nb < 12; nb++)
#pragma unroll
        for (int r = 0; r < 4; r++) acc[nb][r] = 0.f;

    float4 xr[4], wr[3];
#pragma unroll
    for (int it = 0; it < 4; it++) {
        int i = tid + it * 256;
        int r = i >> 3, c4 = i & 7;
        xr[it] = *(const float4*)(x + (size_t)(row0 + r) * CIN + c4 * 4);
    }
#pragma unroll
    for (int m = 0; m < 3; m++) {
        int kk = tid >> 3, c4 = tid & 7;
        wr[m] = *(const float4*)(wmat[m] + (size_t)kk * DHEAD + c4 * 4);
    }
#pragma unroll
    for (int it = 0; it < 4; it++) {
        int i = tid + it * 256;
        int r = i >> 3, c4 = i & 7;
        uint2 p; p.x = pack2(xr[it].x, xr[it].y); p.y = pack2(xr[it].z, xr[it].w);
        *(uint2*)&Xs[0][r * TS + c4 * 4] = p;
    }
#pragma unroll
    for (int m = 0; m < 3; m++) {
        int kk = tid >> 3, c4 = tid & 7;
        uint2 p; p.x = pack2(wr[m].x, wr[m].y); p.y = pack2(wr[m].z, wr[m].w);
        *(uint2*)&Ws[0][kk * WQS + m * 32 + c4 * 4] = p;
    }
    __syncthreads();

    for (int c = 0; c < 8; c++) {
        const int cur = c & 1;

        if (c + 1 < 8) {
            int kc = (c + 1) * 32;
#pragma unroll
            for (int it = 0; it < 4; it++) {
                int i = tid + it * 256;
                int r = i >> 3, c4 = i & 7;
                xr[it] = *(const float4*)(x + (size_t)(row0 + r) * CIN + kc + c4 * 4);
            }
#pragma unroll
            for (int m = 0; m < 3; m++) {
                int kk = tid >> 3, c4 = tid & 7;
                wr[m] = *(const float4*)(wmat[m] + (size_t)(kc + kk) * DHEAD + c4 * 4);
            }
        }

        uint32_t a[2][4];
#pragma unroll
        for (int ks = 0; ks < 2; ks++) {
            uint32_t addr = xs_base + cur * XBUF +
                ((warp * 16 + ((lane >> 3) & 1) * 8 + (lane & 7)) * TS) * 2 +
                (ks * 16 + (lane >> 4) * 8) * 2;
            ldsm4(a[ks], addr);
        }
#pragma unroll
        for (int ks = 0; ks < 2; ks++) {
#pragma unroll
            for (int nbp = 0; nbp < 6; nbp++) {
                uint32_t wb[4];
                uint32_t addr = ws_base + cur * WBUF +
                    ((ks * 16 + ((lane >> 3) & 1) * 8 + (lane & 7)) * WQS) * 2 +
                    (nbp * 16 + (lane >> 4) * 8) * 2;
                ldsm4t(wb, addr);
                mma_f16(acc[2 * nbp],     a[ks], wb[0], wb[1], acc[2 * nbp]);
                mma_f16(acc[2 * nbp + 1], a[ks], wb[2], wb[3], acc[2 * nbp + 1]);
            }
        }

        if (c + 1 < 8) {
#pragma unroll
            for (int it = 0; it < 4; it++) {
                int i = tid + it * 256;
                int r = i >> 3, c4 = i & 7;
                uint2 p; p.x = pack2(xr[it].x, xr[it].y); p.y = pack2(xr[it].z, xr[it].w);
                *(uint2*)&Xs[cur ^ 1][r * TS + c4 * 4] = p;
            }
#pragma unroll
            for (int m = 0; m < 3; m++) {
                int kk = tid >> 3, c4 = tid & 7;
                uint2 p; p.x = pack2(wr[m].x, wr[m].y); p.y = pack2(wr[m].z, wr[m].w);
                *(uint2*)&Ws[cur ^ 1][kk * WQS + m * 32 + c4 * 4] = p;
            }
        }
        __syncthreads();
    }

#pragma unroll
    for (int nb = 0; nb < 12; nb++) {
        int cc = nb * 8 + 2 * tig;
        float b0 = bsm[cc], b1 = bsm[cc + 1];
        int r0 = row0 + warp * 16 + gid;
        __half* dst; int col;
        if (nb < 4)      { dst = g_q; col = cc; }
        else if (nb < 8) { dst = g_k; col = cc - 32; }
        else             { dst = g_v; col = cc - 64; }
        *(uint32_t*)(dst + (size_t)r0 * DHEAD + col) =
            pack2(fmaxf(acc[nb][0] + b0, 0.f), fmaxf(acc[nb][1] + b1, 0.f));
        *(uint32_t*)(dst + (size_t)(r0 + 8) * DHEAD + col) =
            pack2(fmaxf(acc[nb][2] + b0, 0.f), fmaxf(acc[nb][3] + b1, 0.f));
    }
}

// ---------------------------------------------------------------------------
// Kernel 2: split-KV flash attention partial.
// Grid (64, 8, 2) = 1024 CTAs, block 128 (4 warps), 5 CTAs/SM target.
// Mainloop per warp identical to round 13/14. cp.async K/V staging (no regs).
// Writes unnormalized O (fp32) + (m, l) per row per half.
// ---------------------------------------------------------------------------
__global__ void __launch_bounds__(128, 5) attn_partial_kernel()
{
    __shared__ __half Ks[2][MT * TS];      // 2 x 5 KB
    __shared__ __half Vs[2][MT * TS];      // 2 x 5 KB

    const int b   = blockIdx.y;
    const int qt  = blockIdx.x;
    const int z   = blockIdx.z;            // kv half
    const int tid = threadIdx.x;
    const int warp = tid >> 5, lane = tid & 31;
    const int gid = lane >> 2, tig = lane & 3;

    const uint32_t ks_base = (uint32_t)__cvta_generic_to_shared(&Ks[0][0]);
    const uint32_t vs_base = (uint32_t)__cvta_generic_to_shared(&Vs[0][0]);
    const uint32_t BUF = MT * TS * 2;

    const uint32_t ones = (gid == 0) ? 0x3C003C00u : 0u;

    const __half* qg = g_q + ((size_t)b * NPIX + (size_t)qt * QT + warp * 16) * DHEAD;
    const __half* kg = g_k + (size_t)b * NPIX * DHEAD + (size_t)z * KVH * DHEAD;
    const __half* vg = g_v + (size_t)b * NPIX * DHEAD + (size_t)z * KVH * DHEAD;

    uint32_t qa[2][4];
#pragma unroll
    for (int ks = 0; ks < 2; ks++) {
        qa[ks][0] = *(const uint32_t*)(qg + (size_t)(gid)     * DHEAD + ks * 16 + 2 * tig);
        qa[ks][1] = *(const uint32_t*)(qg + (size_t)(gid + 8) * DHEAD + ks * 16 + 2 * tig);
        qa[ks][2] = *(const uint32_t*)(qg + (size_t)(gid)     * DHEAD + ks * 16 + 8 + 2 * tig);
        qa[ks][3] = *(const uint32_t*)(qg + (size_t)(gid + 8) * DHEAD + ks * 16 + 8 + 2 * tig);
    }

    float O[5][4];
#pragma unroll
    for (int nb = 0; nb < 5; nb++)
#pragma unroll
        for (int r = 0; r < 4; r++) O[nb][r] = 0.f;
    float mi0 = -1e30f, mi1 = -1e30f;

    // cp.async staging map: 2 sectors per thread per matrix
    const int s0 = tid, s1 = tid + 128;          // sector ids 0..255
    const int r0s = s0 >> 2, c0s = (s0 & 3) * 8; // row, col(halves)
    const int r1s = s1 >> 2, c1s = (s1 & 3) * 8;

    // prologue: stage tile 0 into buffer 0
    cp16(ks_base + (r0s * TS + c0s) * 2, kg + (size_t)r0s * DHEAD + c0s);
    cp16(ks_base + (r1s * TS + c1s) * 2, kg + (size_t)r1s * DHEAD + c1s);
    cp16(vs_base + (r0s * TS + c0s) * 2, vg + (size_t)r0s * DHEAD + c0s);
    cp16(vs_base + (r1s * TS + c1s) * 2, vg + (size_t)r1s * DHEAD + c1s);
    cp_commit();
    cp_wait0();
    __syncthreads();

    for (int mt = 0; mt < NTILES; mt++) {
        const int cur = mt & 1;

        if (mt + 1 < NTILES) {
            const __half* kt = kg + (size_t)(mt + 1) * MT * DHEAD;
            const __half* vt = vg + (size_t)(mt + 1) * MT * DHEAD;
            const uint32_t kb2 = ks_base + (cur ^ 1) * BUF;
            const uint32_t vb2 = vs_base + (cur ^ 1) * BUF;
            cp16(kb2 + (r0s * TS + c0s) * 2, kt + (size_t)r0s * DHEAD + c0s);
            cp16(kb2 + (r1s * TS + c1s) * 2, kt + (size_t)r1s * DHEAD + c1s);
            cp16(vb2 + (r0s * TS + c0s) * 2, vt + (size_t)r0s * DHEAD + c0s);
            cp16(vb2 + (r1s * TS + c1s) * 2, vt + (size_t)r1s * DHEAD + c1s);
            cp_commit();
        }

        // ---- mma1: S(16x64) = Q K^T ----
        float S[8][4];
#pragma unroll
        for (int nb = 0; nb < 8; nb++) {
#pragma unroll
            for (int r = 0; r < 4; r++) S[nb][r] = 0.f;
            uint32_t kb[4];
            uint32_t addr = ks_base + cur * BUF +
                ((nb * 8 + (lane & 7)) * TS) * 2 + (lane >> 3) * 16;
            ldsm4(kb, addr);
            mma_f16(S[nb], qa[0], kb[0], kb[1], S[nb]);
            mma_f16(S[nb], qa[1], kb[2], kb[3], S[nb]);
        }

        // ---- online softmax (rows gid, gid+8) ----
        float rm0 = -1e30f, rm1 = -1e30f;
#pragma unroll
        for (int nb = 0; nb < 8; nb++) {
            rm0 = fmaxf(rm0, fmaxf(S[nb][0], S[nb][1]));
            rm1 = fmaxf(rm1, fmaxf(S[nb][2], S[nb][3]));
        }
        rm0 = fmaxf(rm0, __shfl_xor_sync(0xffffffffu, rm0, 1));
        rm0 = fmaxf(rm0, __shfl_xor_sync(0xffffffffu, rm0, 2));
        rm1 = fmaxf(rm1, __shfl_xor_sync(0xffffffffu, rm1, 1));
        rm1 = fmaxf(rm1, __shfl_xor_sync(0xffffffffu, rm1, 2));

        float nm0 = fmaxf(mi0, rm0), nm1 = fmaxf(mi1, rm1);
        float corr0 = exp2f((mi0 - nm0) * LOG2E);
        float corr1 = exp2f((mi1 - nm1) * LOG2E);
        mi0 = nm0; mi1 = nm1;
        const float nc0 = nm0 * (-LOG2E), nc1 = nm1 * (-LOG2E);

        uint32_t P[4][4];
#pragma unroll
        for (int nb = 0; nb < 8; nb++) {
            float u0 = fmaf(S[nb][0], LOG2E, nc0);
            float u1 = fmaf(S[nb][1], LOG2E, nc0);
            float u2 = fmaf(S[nb][2], LOG2E, nc1);
            float u3 = fmaf(S[nb][3], LOG2E, nc1);
            int ks2 = nb >> 1, hi = (nb & 1) * 2;
            P[ks2][hi]     = h2exp2(pack2(u0, u1));
            P[ks2][hi + 1] = h2exp2(pack2(u2, u3));
        }

#pragma unroll
        for (int nb = 0; nb < 5; nb++) {
            O[nb][0] *= corr0; O[nb][1] *= corr0;
            O[nb][2] *= corr1; O[nb][3] *= corr1;
        }

        // ---- mma2: O += P V ;  l += P @ ones ----
#pragma unroll
        for (int ks2 = 0; ks2 < 4; ks2++) {
            const uint32_t* a = P[ks2];
#pragma unroll
            for (int dbp = 0; dbp < 2; dbp++) {
                uint32_t vb[4];
                uint32_t addr = vs_base + cur * BUF +
                    ((ks2 * 16 + ((lane >> 3) & 1) * 8 + (lane & 7)) * TS) * 2 +
                    dbp * 32 + (lane >> 4) * 16;
                ldsm4t(vb, addr);
                mma_f16(O[2 * dbp],     a, vb[0], vb[1], O[2 * dbp]);
                mma_f16(O[2 * dbp + 1], a, vb[2], vb[3], O[2 * dbp + 1]);
            }
            mma_f16(O[4], a, ones, ones, O[4]);
        }

        if (mt + 1 < NTILES) cp_wait0();
        __syncthreads();
    }

    // ---- write partials (unnormalized) ----
    const size_t row = (size_t)b * NPIX + (size_t)qt * QT + warp * 16 + gid;
    float* po = g_po + (size_t)z * MROWS * DHEAD;
#pragma unroll
    for (int db = 0; db < 4; db++) {
        int cc = db * 8 + 2 * tig;
        *(float2*)(po + row * DHEAD + cc)       = make_float2(O[db][0], O[db][1]);
        *(float2*)(po + (row + 8) * DHEAD + cc) = make_float2(O[db][2], O[db][3]);
    }
    if (tig == 0) {
        g_ml[(size_t)z * MROWS + row]     = make_float2(mi0, O[4][0]);
        g_ml[(size_t)z * MROWS + row + 8] = make_float2(mi1, O[4][2]);
    }
}

// ---------------------------------------------------------------------------
// Kernel 3: combine partials + output projection.
// Grid (256, 2), block 256. A-fragments built in registers from combined O;
// proj GEMM = round-7 proj structure (ldsmt Wo + 32 mma/warp).
// ---------------------------------------------------------------------------
__global__ void __launch_bounds__(256) combine_proj_kernel(
    const float* __restrict__ Wo,
    const float* __restrict__ bo,
    float* __restrict__ out)
{
    __shared__ __half Wos[32 * WOS];
    __shared__ float bos[128];

    const int tid = threadIdx.x;
    const int warp = tid >> 5, lane = tid & 31;
    const int gid = lane >> 2, tig = lane & 3;
    const int row0 = blockIdx.x * 128;
    const int n0   = blockIdx.y * 128;

    const uint32_t wo_base = (uint32_t)__cvta_generic_to_shared(&Wos[0]);

    if (tid < 128) bos[tid] = bo[n0 + tid];
#pragma unroll
    for (int it = 0; it < 4; it++) {
        int i = tid + it * 256;
        int kk = i >> 5, c4 = i & 31;
        float4 v = *(const float4*)(Wo + (size_t)kk * CIN + n0 + c4 * 4);
        uint2 p; p.x = pack2(v.x, v.y); p.y = pack2(v.z, v.w);
        *(uint2*)&Wos[kk * WOS + c4 * 4] = p;
    }

    // ---- per-thread combine -> A-fragments ----
    const size_t r0 = row0 + warp * 16 + gid;
    const size_t r1 = r0 + 8;
    float2 mlA0 = g_ml[r0],            mlB0 = g_ml[MROWS + r0];
    float2 mlA1 = g_ml[r1],            mlB1 = g_ml[MROWS + r1];
    float m0 = fmaxf(mlA0.x, mlB0.x),  m1 = fmaxf(mlA1.x, mlB1.x);
    float wA0 = exp2f((mlA0.x - m0) * LOG2E), wB0 = exp2f((mlB0.x - m0) * LOG2E);
    float wA1 = exp2f((mlA1.x - m1) * LOG2E), wB1 = exp2f((mlB1.x - m1) * LOG2E);
    float inv0 = 1.f / (mlA0.y * wA0 + mlB0.y * wB0);
    float inv1 = 1.f / (mlA1.y * wA1 + mlB1.y * wB1);
    float c0A = wA0 * inv0, c0B = wB0 * inv0;
    float c1A = wA1 * inv1, c1B = wB1 * inv1;

    uint32_t aep[2][4];
#pragma unroll
    for (int ks = 0; ks < 2; ks++) {
#pragma unroll
        for (int half8 = 0; half8 < 2; half8++) {
            int cc = ks * 16 + half8 * 8 + 2 * tig;
            float2 a0 = *(const float2*)(g_po + r0 * DHEAD + cc);
            float2 b0 = *(const float2*)(g_po + (size_t)MROWS * DHEAD + r0 * DHEAD + cc);
            float2 a1 = *(const float2*)(g_po + r1 * DHEAD + cc);
            float2 b1 = *(const float2*)(g_po + (size_t)MROWS * DHEAD + r1 * DHEAD + cc);
            aep[ks][half8 * 2]     = pack2(a0.x * c0A + b0.x * c0B, a0.y * c0A + b0.y * c0B);
            aep[ks][half8 * 2 + 1] = pack2(a1.x * c1A + b1.x * c1B, a1.y * c1A + b1.y * c1B);
        }
    }
    __syncthreads();

    float acc[16][4];
#pragma unroll
    for (int nb = 0; nb < 16; nb++)
#pragma unroll
        for (int r = 0; r < 4; r++) acc[nb][r] = 0.f;

#pragma unroll
    for (int ks = 0; ks < 2; ks++) {
#pragma unroll
        for (int nbp = 0; nbp < 8; nbp++) {
            uint32_t wb[4];
            uint32_t addr = wo_base +
                ((ks * 16 + ((lane >> 3) & 1) * 8 + (lane & 7)) * WOS) * 2 +
                (nbp * 16 + (lane >> 4) * 8) * 2;
            ldsm4t(wb, addr);
            mma_f16(acc[2 * nbp],     aep[ks], wb[0], wb[1], acc[2 * nbp]);
            mma_f16(acc[2 * nbp + 1], aep[ks], wb[2], wb[3], acc[2 * nbp + 1]);
        }
    }

#pragma unroll
    for (int nb = 0; nb < 16; nb++) {
        int cc = nb * 8 + 2 * tig;
        float b0 = bos[cc], b1 = bos[cc + 1];
        float2 lo, hi;
        lo.x = fmaxf(acc[nb][0] + b0, 0.f); lo.y = fmaxf(acc[nb][1] + b1, 0.f);
        hi.x = fmaxf(acc[nb][2] + b0, 0.f); hi.y = fmaxf(acc[nb][3] + b1, 0.f);
        *(float2*)(out + r0 * CIN + n0 + cc) = lo;
        *(float2*)(out + r1 * CIN + n0 + cc) = hi;
    }
}

// ---------------------------------------------------------------------------
extern "C" void kernel_launch(void* const* d_in, const int* in_sizes, int n_in,
                              void* d_out, int out_size)
{
    const float* x  = (const float*)d_in[0];
    const float* Wq = (const float*)d_in[1];
    const float* bq = (const float*)d_in[2];
    const float* Wk = (const float*)d_in[3];
    const float* bk = (const float*)d_in[4];
    const float* Wv = (const float*)d_in[5];
    const float* bv = (const float*)d_in[6];
    const float* Wo = (const float*)d_in[7];
    const float* bo = (const float*)d_in[8];
    float* out = (float*)d_out;

    qkv_kernel<<<MROWS / 128, 256>>>(x, Wq, bq, Wk, bk, Wv, bv);
    attn_partial_kernel<<<dim3(NPIX / QT, BATCH, 2), 128>>>();
    combine_proj_kernel<<<dim3(MROWS / 128, 2), 256>>>(Wo, bo, out);
}